// round 16
// baseline (speedup 1.0000x reference)
#include <cuda_runtime.h>
#include <math.h>

#define TT 64
#define BB 128
#define NN 256
#define DD 300
#define HD 300
#define GG 1200
#define LL 20
#define ML 320
#define EPSF 1e-8f

// ---------------- device scratch (no allocations allowed) ----------------
// NOTE: original declaration order preserved (buffer layout affects perf via
// the L2 address hash — round 14). New buffers appended at the END only.
static __device__ float g_comb[TT*NN*DD];
static __device__ float g_Xg[TT*NN*GG];
static __device__ float g_hsf[TT*NN*HD];
static __device__ float g_hsb[TT*NN*HD];
static __device__ float g_cf[NN*HD];
static __device__ float g_cb[NN*HD];
static __device__ float g_m[TT*BB*ML];
static __device__ float g_aXf[TT*BB*GG];
static __device__ float g_aXb[TT*BB*GG];
static __device__ float g_ahf[2*BB*HD];
static __device__ float g_ahb[2*BB*HD];
static __device__ float g_acf[BB*HD];
static __device__ float g_acb[BB*HD];
// per-pair matching scratch (pair stride in [2])
static __device__ float g_w1[2][BB*TT*TT];
static __device__ float g_w3[2][BB*TT*TT];
static __device__ int   g_idx1[2][BB*TT];
static __device__ int   g_idx3[2][BB*TT];
static __device__ float g_Pl2[2][TT*BB];
static __device__ float g_Hl2[2][TT*BB];
static __device__ float g_hmean1[2][TT*BB*HD];
static __device__ float g_hmean3[2][TT*BB*HD];
static __device__ float g_pnm[2][TT*BB*LL];
static __device__ float g_hnm[2][TT*BB*LL];
static __device__ float g_y1[BB*600];
static __device__ float g_y2[BB*600];
// appended: per-step agg hidden states + grid-barrier counters
static __device__ float g_ah2f[TT*BB*HD];
static __device__ float g_ah2b[TT*BB*HD];
static __device__ unsigned g_bar1;
static __device__ unsigned g_bar2;

// ---------------- fast math helpers ----------------
__device__ __forceinline__ float sigmf(float x) {
    return __fdividef(1.f, 1.f + __expf(-x));
}
__device__ __forceinline__ float tanh_fast(float x) {
    float t = __expf(-2.f * fabsf(x));
    float y = __fdividef(1.f - t, 1.f + t);
    return copysignf(y, x);
}

// ---------------- kernels ----------------

__global__ void embed_kernel(const int* __restrict__ prem, const int* __restrict__ hyp,
                             const float* __restrict__ E, float* __restrict__ comb)
{
    int i = blockIdx.x * 256 + threadIdx.x;
    if (i >= TT*NN*DD) return;
    int d = i % DD;
    int n = (i / DD) % NN;
    int t = i / (DD*NN);
    int tok = (n < BB) ? prem[t*BB + n] : hyp[t*BB + n - BB];
    comb[i] = E[(size_t)tok*DD + d];
}

// C[M,N] = A[M,K] @ Bw[N,K]^T + bias[N].  (round-7 proven version)
__global__ void gemm_nt2(const float* __restrict__ A, const float* __restrict__ Bw,
                         const float* __restrict__ bias, float* __restrict__ C,
                         int M, int N, int K)
{
    __shared__ __align__(16) float sA[20][68];
    __shared__ __align__(16) float sB[20][68];
    int n0 = blockIdx.x * 64, m0 = blockIdx.y * 64;
    int tid = threadIdx.x, tx = tid & 15, ty = tid >> 4;
    float acc[4][4] = {};
    float hA[5], hB[5];
    int nkt = K / 20;

    #pragma unroll
    for (int u = 0; u < 5; u++) {
        int i = tid + u*256;
        int r = i / 20, c = i % 20;
        hA[u] = A[(size_t)(m0 + r)*K + c];
        int nn = n0 + r; if (nn >= N) nn = N - 1;
        hB[u] = Bw[(size_t)nn*K + c];
    }
    for (int kt = 0; kt < nkt; kt++) {
        #pragma unroll
        for (int u = 0; u < 5; u++) {
            int i = tid + u*256;
            int r = i / 20, c = i % 20;
            sA[c][r] = hA[u];
            sB[c][r] = hB[u];
        }
        __syncthreads();
        if (kt + 1 < nkt) {
            int k0 = (kt + 1) * 20;
            #pragma unroll
            for (int u = 0; u < 5; u++) {
                int i = tid + u*256;
                int r = i / 20, c = i % 20;
                hA[u] = A[(size_t)(m0 + r)*K + k0 + c];
                int nn = n0 + r; if (nn >= N) nn = N - 1;
                hB[u] = Bw[(size_t)nn*K + k0 + c];
            }
        }
        #pragma unroll
        for (int k = 0; k < 20; k++) {
            float4 a = *(const float4*)&sA[k][4*ty];
            float4 b = *(const float4*)&sB[k][4*tx];
            acc[0][0] += a.x*b.x; acc[0][1] += a.x*b.y; acc[0][2] += a.x*b.z; acc[0][3] += a.x*b.w;
            acc[1][0] += a.y*b.x; acc[1][1] += a.y*b.y; acc[1][2] += a.y*b.z; acc[1][3] += a.y*b.w;
            acc[2][0] += a.z*b.x; acc[2][1] += a.z*b.y; acc[2][2] += a.z*b.z; acc[2][3] += a.z*b.w;
            acc[3][0] += a.w*b.x; acc[3][1] += a.w*b.y; acc[3][2] += a.w*b.z; acc[3][3] += a.w*b.w;
        }
        __syncthreads();
    }
    #pragma unroll
    for (int i = 0; i < 4; i++) {
        int mm = m0 + 4*ty + i;
        #pragma unroll
        for (int j = 0; j < 4; j++) {
            int nn = n0 + 4*tx + j;
            if (nn < N) C[(size_t)mm*N + nn] = acc[i][j] + bias[nn];
        }
    }
}

// Both agg input projections in one launch (blockIdx.z selects f/b).
__global__ void gemm_nt2_dual(const float* __restrict__ A,
                              const float* __restrict__ Wf_, const float* __restrict__ bf,
                              const float* __restrict__ Wb_, const float* __restrict__ bb_,
                              float* __restrict__ Cf, float* __restrict__ Cb,
                              int M, int N, int K)
{
    const float* Bw   = blockIdx.z ? Wb_ : Wf_;
    const float* bias = blockIdx.z ? bb_ : bf;
    float* C          = blockIdx.z ? Cb  : Cf;
    __shared__ __align__(16) float sA[20][68];
    __shared__ __align__(16) float sB[20][68];
    int n0 = blockIdx.x * 64, m0 = blockIdx.y * 64;
    int tid = threadIdx.x, tx = tid & 15, ty = tid >> 4;
    float acc[4][4] = {};
    float hA[5], hB[5];
    int nkt = K / 20;

    #pragma unroll
    for (int u = 0; u < 5; u++) {
        int i = tid + u*256;
        int r = i / 20, c = i % 20;
        hA[u] = A[(size_t)(m0 + r)*K + c];
        int nn = n0 + r; if (nn >= N) nn = N - 1;
        hB[u] = Bw[(size_t)nn*K + c];
    }
    for (int kt = 0; kt < nkt; kt++) {
        #pragma unroll
        for (int u = 0; u < 5; u++) {
            int i = tid + u*256;
            int r = i / 20, c = i % 20;
            sA[c][r] = hA[u];
            sB[c][r] = hB[u];
        }
        __syncthreads();
        if (kt + 1 < nkt) {
            int k0 = (kt + 1) * 20;
            #pragma unroll
            for (int u = 0; u < 5; u++) {
                int i = tid + u*256;
                int r = i / 20, c = i % 20;
                hA[u] = A[(size_t)(m0 + r)*K + k0 + c];
                int nn = n0 + r; if (nn >= N) nn = N - 1;
                hB[u] = Bw[(size_t)nn*K + k0 + c];
            }
        }
        #pragma unroll
        for (int k = 0; k < 20; k++) {
            float4 a = *(const float4*)&sA[k][4*ty];
            float4 b = *(const float4*)&sB[k][4*tx];
            acc[0][0] += a.x*b.x; acc[0][1] += a.x*b.y; acc[0][2] += a.x*b.z; acc[0][3] += a.x*b.w;
            acc[1][0] += a.y*b.x; acc[1][1] += a.y*b.y; acc[1][2] += a.y*b.z; acc[1][3] += a.y*b.w;
            acc[2][0] += a.z*b.x; acc[2][1] += a.z*b.y; acc[2][2] += a.z*b.z; acc[2][3] += a.z*b.w;
            acc[3][0] += a.w*b.x; acc[3][1] += a.w*b.y; acc[3][2] += a.w*b.z; acc[3][3] += a.w*b.w;
        }
        __syncthreads();
    }
    #pragma unroll
    for (int i = 0; i < 4; i++) {
        int mm = m0 + 4*ty + i;
        #pragma unroll
        for (int j = 0; j < 4; j++) {
            int nn = n0 + 4*tx + j;
            if (nn < N) C[(size_t)mm*N + nn] = acc[i][j] + bias[nn];
        }
    }
}

// Persistent BiLSTM: all 64 timesteps in ONE kernel with a grid barrier between
// steps. Grid (19, ROWS/RT, 2) = 152 blocks; __launch_bounds__(256,2) guarantees
// all blocks co-resident (296 slots). Compute body identical to lstm_step4.
// BIG: h stored by time index in hs (full sequence). !BIG: h stored by step s.
template<int RT, int RPT, bool BIG>
__global__ void __launch_bounds__(256, 2) lstm_persist(
    const float* __restrict__ xg0, const float* __restrict__ xg1,
    const float* __restrict__ Whh_f, const float* __restrict__ Whh_b,
    float* __restrict__ hs_f, float* __restrict__ hs_b,
    float* __restrict__ c_f, float* __restrict__ c_b,
    unsigned* __restrict__ bar)
{
    constexpr int NT = 256;
    constexpr int NH = (30*RT + NT - 1) / NT;
    constexpr int NW = (30*64 + NT - 1) / NT;
    constexpr int ROWS = BIG ? NN : BB;

    int dir = blockIdx.z;
    const float* xgb = dir ? xg1 : xg0;
    const float* Whh = dir ? Whh_b : Whh_f;
    float* hs = dir ? hs_b : hs_f;
    float* cs = dir ? c_b  : c_f;

    int j0 = blockIdx.x * 16;
    int r0 = blockIdx.y * RT;
    int tx = threadIdx.x;
    int ty = threadIdx.y;
    int tid = ty * 16 + tx;
    unsigned nb = gridDim.x * gridDim.y * gridDim.z;

    __shared__ __align__(16) float sH[30][RT + 4];
    __shared__ __align__(16) float sW[30][68];

    for (int s = 0; s < 64; s++) {
        int first = (s == 0);
        int t_in = dir ? 63 - s : s;                 // time index for xg and (BIG) h out
        const float* xg = xgb + (size_t)t_in * ROWS * GG;
        const float* hp;
        float* ho;
        if constexpr (BIG) {
            int t_prev = dir ? 64 - s : s - 1;
            hp = hs + (size_t)t_prev * ROWS * HD;    // unused when first
            ho = hs + (size_t)t_in  * ROWS * HD;
        } else {
            hp = hs + (size_t)(s - 1) * ROWS * HD;   // unused when first
            ho = hs + (size_t)s       * ROWS * HD;
        }

        float acc[4][RPT] = {};
        if (!first) {
            float hA[NH], hW[NW];
            #pragma unroll
            for (int u = 0; u < NH; u++) {
                int i = tid + u*NT;
                if (i < 30*RT) { int r = i/30, c = i%30; hA[u] = hp[(size_t)(r0 + r)*HD + c]; }
            }
            #pragma unroll
            for (int u = 0; u < NW; u++) {
                int i = tid + u*NT;
                if (i < 30*64) {
                    int rr = i/30, c = i%30;
                    int gg = rr & 3, jl = rr >> 2;
                    int jj = j0 + jl; if (jj >= HD) jj = HD - 1;
                    hW[u] = Whh[(size_t)(gg*HD + jj)*HD + c];
                }
            }
            for (int kt = 0; kt < 10; kt++) {
                #pragma unroll
                for (int u = 0; u < NH; u++) {
                    int i = tid + u*NT;
                    if (i < 30*RT) { int r = i/30, c = i%30; sH[c][r] = hA[u]; }
                }
                #pragma unroll
                for (int u = 0; u < NW; u++) {
                    int i = tid + u*NT;
                    if (i < 30*64) { int rr = i/30, c = i%30; sW[c][rr] = hW[u]; }
                }
                __syncthreads();
                if (kt < 9) {
                    int k0 = (kt + 1) * 30;
                    #pragma unroll
                    for (int u = 0; u < NH; u++) {
                        int i = tid + u*NT;
                        if (i < 30*RT) { int r = i/30, c = i%30; hA[u] = hp[(size_t)(r0 + r)*HD + k0 + c]; }
                    }
                    #pragma unroll
                    for (int u = 0; u < NW; u++) {
                        int i = tid + u*NT;
                        if (i < 30*64) {
                            int rr = i/30, c = i%30;
                            int gg = rr & 3, jl = rr >> 2;
                            int jj = j0 + jl; if (jj >= HD) jj = HD - 1;
                            hW[u] = Whh[(size_t)(gg*HD + jj)*HD + k0 + c];
                        }
                    }
                }
                #pragma unroll
                for (int k = 0; k < 30; k++) {
                    float4 b = *(const float4*)&sW[k][4*tx];
                    if constexpr (RPT == 4) {
                        float4 a = *(const float4*)&sH[k][4*ty];
                        acc[0][0] += b.x*a.x; acc[0][1] += b.x*a.y; acc[0][2] += b.x*a.z; acc[0][3] += b.x*a.w;
                        acc[1][0] += b.y*a.x; acc[1][1] += b.y*a.y; acc[1][2] += b.y*a.z; acc[1][3] += b.y*a.w;
                        acc[2][0] += b.z*a.x; acc[2][1] += b.z*a.y; acc[2][2] += b.z*a.z; acc[2][3] += b.z*a.w;
                        acc[3][0] += b.w*a.x; acc[3][1] += b.w*a.y; acc[3][2] += b.w*a.z; acc[3][3] += b.w*a.w;
                    } else {
                        float2 a = *(const float2*)&sH[k][2*ty];
                        acc[0][0] += b.x*a.x; acc[0][1] += b.x*a.y;
                        acc[1][0] += b.y*a.x; acc[1][1] += b.y*a.y;
                        acc[2][0] += b.z*a.x; acc[2][1] += b.z*a.y;
                        acc[3][0] += b.w*a.x; acc[3][1] += b.w*a.y;
                    }
                }
                __syncthreads();
            }
        }
        int j = j0 + tx;
        if (j < HD) {
            #pragma unroll
            for (int r = 0; r < RPT; r++) {
                int row = r0 + RPT*ty + r;
                const float* xr = xg + (size_t)row*GG + j;
                float gi = acc[0][r] + xr[0];
                float gf = acc[1][r] + xr[300];
                float gg = acc[2][r] + xr[600];
                float go = acc[3][r] + xr[900];
                float cp = first ? 0.f : cs[row*HD + j];
                float cn = sigmf(gf)*cp + sigmf(gi)*tanh_fast(gg);
                cs[row*HD + j] = cn;
                ho[row*HD + j] = sigmf(go)*tanh_fast(cn);
            }
        }
        // grid barrier (skip after the last step)
        if (s < 63) {
            __syncthreads();
            if (tid == 0) {
                __threadfence();                       // release h writes
                atomicAdd(bar, 1u);
                volatile unsigned* vb = (volatile unsigned*)bar;
                unsigned target = (unsigned)(s + 1) * nb;
                while (*vb < target) { }
                __threadfence();
            }
            __syncthreads();
        }
    }
}

// Fused L2 + perspective-weighted norms, both pairs: grid (TT*BB, 2), 128 threads.
__global__ void l2pn_kernel(const float* __restrict__ hsf, const float* __restrict__ hsb,
                            const float* __restrict__ mp_W,
                            float* __restrict__ pnm, float* __restrict__ hnm,
                            float* __restrict__ Pl2, float* __restrict__ Hl2)
{
    int pair = blockIdx.y;
    const float* base = pair ? hsb : hsf;
    const float* Wm = mp_W + (pair ? 30000 : 6000);
    float* po = pnm + (size_t)pair*TT*BB*LL;
    float* ho = hnm + (size_t)pair*TT*BB*LL;
    float* Po = Pl2 + pair*TT*BB;
    float* Ho = Hl2 + pair*TT*BB;

    int tb = blockIdx.x;
    int t = tb / BB, b = tb % BB;
    int warp = threadIdx.x >> 5, lane = threadIdx.x & 31;
    const float* prow = base + (size_t)t*NN*HD + b*HD;
    const float* hrow = prow + BB*HD;
    float p2[10], h2[10];
    #pragma unroll
    for (int u = 0; u < 10; u++) {
        int h = lane + 32*u;
        float pv = (h < HD) ? prow[h] : 0.f;
        float hv = (h < HD) ? hrow[h] : 0.f;
        p2[u] = pv*pv; h2[u] = hv*hv;
    }
    if (warp < 2) {
        float s = 0.f;
        #pragma unroll
        for (int u = 0; u < 10; u++) s += (warp ? h2[u] : p2[u]);
        for (int o = 16; o; o >>= 1) s += __shfl_down_sync(0xffffffffu, s, o);
        if (lane == 0) (warp ? Ho : Po)[t*BB + b] = sqrtf(s);
    }
    for (int l = warp; l < LL; l += 4) {
        float ap = 0.f, ah = 0.f;
        #pragma unroll
        for (int u = 0; u < 10; u++) {
            int h = lane + 32*u;
            float wv = (h < HD) ? Wm[l*HD + h] : 0.f;
            float w2 = wv*wv;
            ap += p2[u]*w2; ah += h2[u]*w2;
        }
        for (int o = 16; o; o >>= 1) {
            ap += __shfl_down_sync(0xffffffffu, ap, o);
            ah += __shfl_down_sync(0xffffffffu, ah, o);
        }
        if (lane == 0) { po[tb*LL + l] = sqrtf(ap); ho[tb*LL + l] = sqrtf(ah); }
    }
}

// Cosine attention for both pairs and both directions: grid (BB, 2).
__global__ void att2_kernel(const float* __restrict__ hsf, const float* __restrict__ hsb,
                            const float* __restrict__ Pl2, const float* __restrict__ Hl2,
                            float* __restrict__ w1out, int* __restrict__ idx1out,
                            float* __restrict__ w3out, int* __restrict__ idx3out)
{
    int pair = blockIdx.y;
    const float* A = (pair ? hsb : hsf);
    const float* B = A + BB*HD;
    const float* Al2 = Pl2 + pair*TT*BB;
    const float* Bl2 = Hl2 + pair*TT*BB;
    float* w1o = w1out + (size_t)pair*BB*TT*TT;
    float* w3o = w3out + (size_t)pair*BB*TT*TT;
    int* i1o = idx1out + pair*BB*TT;
    int* i3o = idx3out + pair*BB*TT;

    int b = blockIdx.x;
    __shared__ __align__(16) float sP[20][68], sH[20][68];
    __shared__ float sAtt[64][65];
    __shared__ float sSumR[64];
    __shared__ float sSumC[64];
    int tid = threadIdx.x, tx = tid & 15, ty = tid >> 4;
    float acc[4][4] = {};
    const int TS = NN*HD;
    for (int kt = 0; kt < 15; kt++) {
        int k0 = kt*20;
        #pragma unroll
        for (int u = 0; u < 5; u++) {
            int i = tid + u*256;
            int r = i / 20, c = i % 20;
            sP[c][r] = A[(size_t)r*TS + b*HD + k0 + c];
            sH[c][r] = B[(size_t)r*TS + b*HD + k0 + c];
        }
        __syncthreads();
        #pragma unroll
        for (int k = 0; k < 20; k++) {
            float4 a = *(const float4*)&sP[k][4*ty];
            float4 bb = *(const float4*)&sH[k][4*tx];
            acc[0][0] += a.x*bb.x; acc[0][1] += a.x*bb.y; acc[0][2] += a.x*bb.z; acc[0][3] += a.x*bb.w;
            acc[1][0] += a.y*bb.x; acc[1][1] += a.y*bb.y; acc[1][2] += a.y*bb.z; acc[1][3] += a.y*bb.w;
            acc[2][0] += a.z*bb.x; acc[2][1] += a.z*bb.y; acc[2][2] += a.z*bb.z; acc[2][3] += a.z*bb.w;
            acc[3][0] += a.w*bb.x; acc[3][1] += a.w*bb.y; acc[3][2] += a.w*bb.z; acc[3][3] += a.w*bb.w;
        }
        __syncthreads();
    }
    #pragma unroll
    for (int i = 0; i < 4; i++) {
        int t = 4*ty + i;
        float pn = Al2[t*BB + b] + EPSF;
        #pragma unroll
        for (int j = 0; j < 4; j++) {
            int s = 4*tx + j;
            sAtt[t][s] = acc[i][j] / (pn * (Bl2[s*BB + b] + EPSF));
        }
    }
    __syncthreads();
    if (tid < 64) {
        float sum = 0.f, best = -1e30f; int bi = 0;
        for (int s = 0; s < 64; s++) {
            float v = sAtt[tid][s];
            sum += v;
            if (v > best) { best = v; bi = s; }
        }
        sSumR[tid] = sum + EPSF;
        i1o[b*64 + tid] = bi;
    } else if (tid < 128) {
        int t = tid - 64;
        float sum = 0.f, best = -1e30f; int bi = 0;
        for (int s = 0; s < 64; s++) {
            float v = sAtt[s][t];
            sum += v;
            if (v > best) { best = v; bi = s; }
        }
        sSumC[t] = sum + EPSF;
        i3o[b*64 + t] = bi;
    }
    __syncthreads();
    for (int i = tid; i < 4096; i += 256) {
        int t = i >> 6, s = i & 63;
        w1o[b*4096 + i] = sAtt[t][s] / sSumR[t];
        w3o[b*4096 + i] = sAtt[s][t] / sSumC[t];
    }
}

// hmean for all 4 (pair, dir) variants: grid (BB, 2, 2). y=dir, z=pair.
__global__ void hmean_kernel(const float* __restrict__ hsf, const float* __restrict__ hsb,
                             const float* __restrict__ w1, const float* __restrict__ w3,
                             float* __restrict__ hmean1, float* __restrict__ hmean3)
{
    int pair = blockIdx.z, dir = blockIdx.y;
    const float* base = pair ? hsb : hsf;
    const float* Hm = dir ? base : base + BB*HD;
    const float* w  = (dir ? w3 : w1) + (size_t)pair*BB*TT*TT;
    float* hout = (dir ? hmean3 : hmean1) + (size_t)pair*TT*BB*HD;

    int b = blockIdx.x;
    __shared__ float sW[64][65];
    int tid = threadIdx.x;
    for (int i = tid; i < 4096; i += 256) sW[i >> 6][i & 63] = w[b*4096 + i];
    __syncthreads();
    int tx = tid & 31, ty = tid >> 5;
    const int TS = NN*HD;
    for (int hc = 0; hc < 10; hc++) {
        int h = hc*32 + tx;
        bool valid = h < HD;
        float acc[8] = {};
        for (int s = 0; s < 64; s++) {
            float hv = valid ? Hm[(size_t)s*TS + b*HD + h] : 0.f;
            #pragma unroll
            for (int i = 0; i < 8; i++) acc[i] += sW[ty + 8*i][s] * hv;
        }
        if (valid) {
            #pragma unroll
            for (int i = 0; i < 8; i++) {
                int t = ty + 8*i;
                hout[((size_t)t*BB + b)*HD + h] = acc[i];
            }
        }
    }
}

// Shared-transpose maxp for both pairs: grid (BB, LL, 2).
__global__ void maxp3_kernel(const float* __restrict__ hsf, const float* __restrict__ hsb,
                             const float* __restrict__ mp_W,
                             const float* __restrict__ pnm, const float* __restrict__ hnm,
                             float* __restrict__ mout)
{
    int pair = blockIdx.z;
    const float* A = pair ? hsb : hsf;
    const float* B = A + BB*HD;
    const float* Wm = mp_W + (pair ? 30000 : 6000);
    const float* na = pnm + (size_t)pair*TT*BB*LL;
    const float* nb = hnm + (size_t)pair*TT*BB*LL;
    int moff1 = pair ? 80 : 0;
    int moff3 = pair ? 240 : 160;

    int b = blockIdx.x, l = blockIdx.y;
    __shared__ __align__(16) float sP[20][68], sH[20][68];
    __shared__ float sRedR[64][17];
    __shared__ float sRedC[64][17];
    int tid = threadIdx.x, tx = tid & 15, ty = tid >> 4;
    float acc[4][4] = {};
    const int TS = NN*HD;
    float hP[5], hHv[5];
    #pragma unroll
    for (int u = 0; u < 5; u++) {
        int i = tid + u*256;
        int r = i / 20, c = i % 20;
        float w = Wm[l*HD + c];
        hP[u]  = A[(size_t)r*TS + b*HD + c] * w * w;
        hHv[u] = B[(size_t)r*TS + b*HD + c];
    }
    for (int kt = 0; kt < 15; kt++) {
        #pragma unroll
        for (int u = 0; u < 5; u++) {
            int i = tid + u*256;
            int r = i / 20, c = i % 20;
            sP[c][r] = hP[u];
            sH[c][r] = hHv[u];
        }
        __syncthreads();
        if (kt < 14) {
            int k0 = (kt + 1)*20;
            #pragma unroll
            for (int u = 0; u < 5; u++) {
                int i = tid + u*256;
                int r = i / 20, c = i % 20;
                float w = Wm[l*HD + k0 + c];
                hP[u]  = A[(size_t)r*TS + b*HD + k0 + c] * w * w;
                hHv[u] = B[(size_t)r*TS + b*HD + k0 + c];
            }
        }
        #pragma unroll
        for (int k = 0; k < 20; k++) {
            float4 a = *(const float4*)&sP[k][4*ty];
            float4 bb = *(const float4*)&sH[k][4*tx];
            acc[0][0] += a.x*bb.x; acc[0][1] += a.x*bb.y; acc[0][2] += a.x*bb.z; acc[0][3] += a.x*bb.w;
            acc[1][0] += a.y*bb.x; acc[1][1] += a.y*bb.y; acc[1][2] += a.y*bb.z; acc[1][3] += a.y*bb.w;
            acc[2][0] += a.z*bb.x; acc[2][1] += a.z*bb.y; acc[2][2] += a.z*bb.z; acc[2][3] += a.z*bb.w;
            acc[3][0] += a.w*bb.x; acc[3][1] += a.w*bb.y; acc[3][2] += a.w*bb.z; acc[3][3] += a.w*bb.w;
        }
        __syncthreads();
    }
    float colmax[4] = {-1e30f, -1e30f, -1e30f, -1e30f};
    #pragma unroll
    for (int i = 0; i < 4; i++) {
        int t = 4*ty + i;
        float nat = na[(t*BB + b)*LL + l];
        float rmx = -1e30f;
        #pragma unroll
        for (int j = 0; j < 4; j++) {
            int s = 4*tx + j;
            float v = acc[i][j] / (nat * nb[(s*BB + b)*LL + l] + EPSF);
            rmx = fmaxf(rmx, v);
            colmax[j] = fmaxf(colmax[j], v);
        }
        sRedR[t][tx] = rmx;
    }
    #pragma unroll
    for (int j = 0; j < 4; j++) {
        int s = 4*tx + j;
        sRedC[s][ty] = colmax[j];
    }
    __syncthreads();
    if (tid < 64) {
        float mx = -1e30f;
        #pragma unroll
        for (int j = 0; j < 16; j++) mx = fmaxf(mx, sRedR[tid][j]);
        mout[((size_t)tid*BB + b)*ML + moff1 + 20 + l] = mx;
    } else if (tid < 128) {
        int s = tid - 64;
        float mx = -1e30f;
        #pragma unroll
        for (int j = 0; j < 16; j++) mx = fmaxf(mx, sRedC[s][j]);
        mout[((size_t)s*BB + b)*ML + moff3 + 20 + l] = mx;
    }
}

// full / attm / maxattm fused, all 4 (pair, dir) variants: grid (TT*BB, 2, 2).
__global__ void mpcomb_kernel(const float* __restrict__ hsf, const float* __restrict__ hsb,
                              const float* __restrict__ mp_W,
                              const float* __restrict__ hmean1, const float* __restrict__ hmean3,
                              const int* __restrict__ idx1, const int* __restrict__ idx3,
                              float* __restrict__ mout)
{
    int pair = blockIdx.z, dir = blockIdx.y;
    const float* base = pair ? hsb : hsf;
    const float* A = base;
    const float* Bm = base + BB*HD;
    const int TS = NN*HD;
    const float* Vb;
    if (pair == 0) Vb = dir ? (hsf + (size_t)63*TS) : (hsf + (size_t)63*TS + BB*HD);
    else           Vb = dir ? hsb : (hsb + BB*HD);
    const float* P  = dir ? Bm : A;
    const float* Hm = dir ? A  : Bm;
    const float* hmean = (dir ? hmean3 : hmean1) + (size_t)pair*TT*BB*HD;
    const int* idx = (dir ? idx3 : idx1) + pair*BB*TT;
    const float* Wf  = mp_W + (pair ? 24000 : 0);
    const float* Wa  = Wf + 12000;
    const float* Wma = Wf + 18000;
    int moff = pair ? (dir ? 240 : 80) : (dir ? 160 : 0);

    int tb = blockIdx.x;
    int t = tb / BB, b = tb % BB;
    int warp = threadIdx.x >> 5, lane = threadIdx.x & 31;
    int si = idx[b*64 + t];
    const float* prow = P  + (size_t)t*TS + b*HD;
    const float* vrow = Vb + (size_t)b*HD;
    const float* mrow = hmean + (size_t)tb*HD;
    const float* xrow = Hm + (size_t)si*TS + b*HD;
    float pv[10], p2[10], v2[10], phm[10], hm2[10], phx[10], hx2[10];
    #pragma unroll
    for (int u = 0; u < 10; u++) {
        int h = lane + 32*u;
        float p  = (h < HD) ? prow[h] : 0.f;
        float v  = (h < HD) ? vrow[h] : 0.f;
        float hm = (h < HD) ? mrow[h] : 0.f;
        float hx = (h < HD) ? xrow[h] : 0.f;
        pv[u] = p*v;  p2[u] = p*p;   v2[u] = v*v;
        phm[u] = p*hm; hm2[u] = hm*hm;
        phx[u] = p*hx; hx2[u] = hx*hx;
    }
    for (int l = warp; l < LL; l += 4) {
        float nf = 0, pf = 0, vf = 0, na = 0, pa = 0, qa = 0, nm = 0, pm = 0, qm = 0;
        #pragma unroll
        for (int u = 0; u < 10; u++) {
            int h = lane + 32*u;
            float wfv = (h < HD) ? Wf [l*HD + h] : 0.f; float wf2 = wfv*wfv;
            float wav = (h < HD) ? Wa [l*HD + h] : 0.f; float wa2 = wav*wav;
            float wmv = (h < HD) ? Wma[l*HD + h] : 0.f; float wm2 = wmv*wmv;
            nf += pv[u]*wf2;  pf += p2[u]*wf2;  vf += v2[u]*wf2;
            na += phm[u]*wa2; pa += p2[u]*wa2;  qa += hm2[u]*wa2;
            nm += phx[u]*wm2; pm += p2[u]*wm2;  qm += hx2[u]*wm2;
        }
        for (int o = 16; o; o >>= 1) {
            nf += __shfl_down_sync(0xffffffffu, nf, o);
            pf += __shfl_down_sync(0xffffffffu, pf, o);
            vf += __shfl_down_sync(0xffffffffu, vf, o);
            na += __shfl_down_sync(0xffffffffu, na, o);
            pa += __shfl_down_sync(0xffffffffu, pa, o);
            qa += __shfl_down_sync(0xffffffffu, qa, o);
            nm += __shfl_down_sync(0xffffffffu, nm, o);
            pm += __shfl_down_sync(0xffffffffu, pm, o);
            qm += __shfl_down_sync(0xffffffffu, qm, o);
        }
        if (lane == 0) {
            size_t basei = (size_t)tb*ML + moff;
            mout[basei + l]      = nf / (sqrtf(pf)*sqrtf(vf) + EPSF);
            mout[basei + 40 + l] = na / (sqrtf(pa)*sqrtf(qa) + EPSF);
            mout[basei + 60 + l] = nm / (sqrtf(pm)*sqrtf(qm) + EPSF);
        }
    }
}

// y = [relu]( bn(x) @ W^T + b ),  bn applied to the input row. One row per block.
__global__ void fc_kernel(const float* __restrict__ xa, const float* __restrict__ xb,
                          int Kin,
                          const float* __restrict__ W, const float* __restrict__ bias,
                          const float* __restrict__ gamma, const float* __restrict__ beta,
                          float inv,
                          float* __restrict__ y, int Co, int relu)
{
    __shared__ float sx[600];
    int r = blockIdx.x;
    int half = Kin / 2;
    for (int k = threadIdx.x; k < Kin; k += blockDim.x) {
        float xv;
        if (xb) xv = (k < half) ? xa[r*half + k] : xb[r*half + k - half];
        else    xv = xa[r*Kin + k];
        sx[k] = gamma[k]*xv*inv + beta[k];
    }
    __syncthreads();
    for (int c = threadIdx.x; c < Co; c += blockDim.x) {
        float a = bias[c];
        for (int k = 0; k < Kin; k++) a += sx[k] * W[(size_t)c*Kin + k];
        y[r*Co + c] = (relu && a < 0.f) ? 0.f : a;
    }
}

// ---------------- host orchestration ----------------

extern "C" void kernel_launch(void* const* d_in, const int* in_sizes, int n_in,
                              void* d_out, int out_size)
{
    const int*   premise    = (const int*)d_in[0];
    const int*   hypothesis = (const int*)d_in[1];
    const float* embed_W    = (const float*)d_in[2];
    const float* cell_Wih   = (const float*)d_in[3];
    const float* cell_Whh   = (const float*)d_in[4];
    const float* cell_b     = (const float*)d_in[5];
    const float* mp_W       = (const float*)d_in[6];
    const float* agg_Wih_f  = (const float*)d_in[7];
    const float* agg_Whh_f  = (const float*)d_in[8];
    const float* agg_b_f    = (const float*)d_in[9];
    const float* agg_Wih_b  = (const float*)d_in[10];
    const float* agg_Whh_b  = (const float*)d_in[11];
    const float* agg_b_b    = (const float*)d_in[12];
    const float* bn_gamma   = (const float*)d_in[13];
    const float* bn_beta    = (const float*)d_in[14];
    const float* mlp_W1     = (const float*)d_in[15];
    const float* mlp_b1     = (const float*)d_in[16];
    const float* mlp_W2     = (const float*)d_in[17];
    const float* mlp_b2     = (const float*)d_in[18];
    const float* out_W      = (const float*)d_in[19];
    const float* out_b      = (const float*)d_in[20];
    float* outp = (float*)d_out;

    float *comb, *Xg, *hsf, *hsb, *cf, *cb, *mbuf, *aXf, *aXb;
    float *acf, *acb, *w1, *w3, *Pl2, *Hl2;
    float *hmean1, *hmean3, *pnm, *hnm, *y1, *y2;
    float *ah2f, *ah2b;
    unsigned *bar1, *bar2;
    int *idx1, *idx3;
    cudaGetSymbolAddress((void**)&comb, g_comb);
    cudaGetSymbolAddress((void**)&Xg,   g_Xg);
    cudaGetSymbolAddress((void**)&hsf,  g_hsf);
    cudaGetSymbolAddress((void**)&hsb,  g_hsb);
    cudaGetSymbolAddress((void**)&cf,   g_cf);
    cudaGetSymbolAddress((void**)&cb,   g_cb);
    cudaGetSymbolAddress((void**)&mbuf, g_m);
    cudaGetSymbolAddress((void**)&aXf,  g_aXf);
    cudaGetSymbolAddress((void**)&aXb,  g_aXb);
    cudaGetSymbolAddress((void**)&acf,  g_acf);
    cudaGetSymbolAddress((void**)&acb,  g_acb);
    cudaGetSymbolAddress((void**)&w1,   g_w1);
    cudaGetSymbolAddress((void**)&w3,   g_w3);
    cudaGetSymbolAddress((void**)&idx1, g_idx1);
    cudaGetSymbolAddress((void**)&idx3, g_idx3);
    cudaGetSymbolAddress((void**)&Pl2,  g_Pl2);
    cudaGetSymbolAddress((void**)&Hl2,  g_Hl2);
    cudaGetSymbolAddress((void**)&hmean1, g_hmean1);
    cudaGetSymbolAddress((void**)&hmean3, g_hmean3);
    cudaGetSymbolAddress((void**)&pnm,  g_pnm);
    cudaGetSymbolAddress((void**)&hnm,  g_hnm);
    cudaGetSymbolAddress((void**)&y1,   g_y1);
    cudaGetSymbolAddress((void**)&y2,   g_y2);
    cudaGetSymbolAddress((void**)&ah2f, g_ah2f);
    cudaGetSymbolAddress((void**)&ah2b, g_ah2b);
    cudaGetSymbolAddress((void**)&bar1, g_bar1);
    cudaGetSymbolAddress((void**)&bar2, g_bar2);

    // 1. embedding gather -> comb (T,256,300)
    embed_kernel<<<(TT*NN*DD + 255)/256, 256>>>(premise, hypothesis, embed_W, comb);

    // 2. input projection for LSTM1, all timesteps at once
    gemm_nt2<<<dim3(19, 256), 256>>>(comb, cell_Wih, cell_b, Xg, TT*NN, GG, DD);

    // 3. BiLSTM1 recurrence: ONE persistent kernel, 64 steps, grid barrier
    cudaMemsetAsync(bar1, 0, sizeof(unsigned));
    lstm_persist<64, 4, true><<<dim3(19, 4, 2), dim3(16, 16)>>>(
        Xg, Xg, cell_Whh, cell_Whh, hsf, hsb, cf, cb, bar1);

    // 4. multi-perspective matching — both transpose pairs per launch
    l2pn_kernel <<<dim3(TT*BB, 2), 128>>>(hsf, hsb, mp_W, pnm, hnm, Pl2, Hl2);
    att2_kernel <<<dim3(BB, 2), 256>>>(hsf, hsb, Pl2, Hl2, w1, idx1, w3, idx3);
    hmean_kernel<<<dim3(BB, 2, 2), 256>>>(hsf, hsb, w1, w3, hmean1, hmean3);
    maxp3_kernel<<<dim3(BB, LL, 2), 256>>>(hsf, hsb, mp_W, pnm, hnm, mbuf);
    mpcomb_kernel<<<dim3(TT*BB, 2, 2), 128>>>(hsf, hsb, mp_W, hmean1, hmean3,
                                              idx1, idx3, mbuf);

    // 5. aggregation input projections (both in one launch)
    gemm_nt2_dual<<<dim3(19, 128, 2), 256>>>(mbuf, agg_Wih_f, agg_b_f,
                                             agg_Wih_b, agg_b_b,
                                             aXf, aXb, TT*BB, GG, ML);

    // 6. aggregation BiLSTM: ONE persistent kernel, per-step h storage
    cudaMemsetAsync(bar2, 0, sizeof(unsigned));
    lstm_persist<32, 2, false><<<dim3(19, 4, 2), dim3(16, 16)>>>(
        aXf, aXb, agg_Whh_f, agg_Whh_b, ah2f, ah2b, acf, acb, bar2);
    const float* af = ah2f + (size_t)63*BB*HD;
    const float* ab = ah2b + (size_t)63*BB*HD;

    // 7. head: bn -> fc -> relu (x2) -> bn -> out
    float inv = (float)(1.0 / sqrt(1.0 + 1e-5));
    fc_kernel<<<BB, 256>>>(af, ab, 600, mlp_W1, mlp_b1, bn_gamma,        bn_beta,        inv, y1, 600, 1);
    fc_kernel<<<BB, 256>>>(y1, nullptr, 600, mlp_W2, mlp_b2, bn_gamma + 600,  bn_beta + 600,  inv, y2, 600, 1);
    fc_kernel<<<BB, 256>>>(y2, nullptr, 600, out_W,  out_b,  bn_gamma + 1200, bn_beta + 1200, inv, outp, 3, 0);
}

// round 17
// speedup vs baseline: 1.0726x; 1.0726x over previous
#include <cuda_runtime.h>
#include <math.h>

#define TT 64
#define BB 128
#define NN 256
#define DD 300
#define HD 300
#define GG 1200
#define LL 20
#define ML 320
#define EPSF 1e-8f

// ---------------- device scratch (no allocations allowed) ----------------
// NOTE: original declaration order preserved (buffer layout affects perf via
// the L2 address hash — round 14 lesson).
static __device__ float g_comb[TT*NN*DD];
static __device__ float g_Xg[TT*NN*GG];
static __device__ float g_hsf[TT*NN*HD];
static __device__ float g_hsb[TT*NN*HD];
static __device__ float g_cf[NN*HD];
static __device__ float g_cb[NN*HD];
static __device__ float g_m[TT*BB*ML];
static __device__ float g_aXf[TT*BB*GG];
static __device__ float g_aXb[TT*BB*GG];
static __device__ float g_ahf[2*BB*HD];
static __device__ float g_ahb[2*BB*HD];
static __device__ float g_acf[BB*HD];
static __device__ float g_acb[BB*HD];
// per-pair matching scratch (pair stride in [2])
static __device__ float g_w1[2][BB*TT*TT];
static __device__ float g_w3[2][BB*TT*TT];
static __device__ int   g_idx1[2][BB*TT];
static __device__ int   g_idx3[2][BB*TT];
static __device__ float g_Pl2[2][TT*BB];
static __device__ float g_Hl2[2][TT*BB];
static __device__ float g_hmean1[2][TT*BB*HD];
static __device__ float g_hmean3[2][TT*BB*HD];
static __device__ float g_pnm[2][TT*BB*LL];
static __device__ float g_hnm[2][TT*BB*LL];
static __device__ float g_y1[BB*600];
static __device__ float g_y2[BB*600];

// ---------------- fast math helpers ----------------
__device__ __forceinline__ float sigmf(float x) {
    return __fdividef(1.f, 1.f + __expf(-x));
}
__device__ __forceinline__ float tanh_fast(float x) {
    float t = __expf(-2.f * fabsf(x));
    float y = __fdividef(1.f - t, 1.f + t);
    return copysignf(y, x);
}

// ---------------- kernels ----------------

__global__ void embed_kernel(const int* __restrict__ prem, const int* __restrict__ hyp,
                             const float* __restrict__ E, float* __restrict__ comb)
{
    int i = blockIdx.x * 256 + threadIdx.x;
    if (i >= TT*NN*DD) return;
    int d = i % DD;
    int n = (i / DD) % NN;
    int t = i / (DD*NN);
    int tok = (n < BB) ? prem[t*BB + n] : hyp[t*BB + n - BB];
    comb[i] = E[(size_t)tok*DD + d];
}

// C[M,N] = A[M,K] @ Bw[N,K]^T + bias[N].  (round-7 proven version)
__global__ void gemm_nt2(const float* __restrict__ A, const float* __restrict__ Bw,
                         const float* __restrict__ bias, float* __restrict__ C,
                         int M, int N, int K)
{
    __shared__ __align__(16) float sA[20][68];
    __shared__ __align__(16) float sB[20][68];
    int n0 = blockIdx.x * 64, m0 = blockIdx.y * 64;
    int tid = threadIdx.x, tx = tid & 15, ty = tid >> 4;
    float acc[4][4] = {};
    float hA[5], hB[5];
    int nkt = K / 20;

    #pragma unroll
    for (int u = 0; u < 5; u++) {
        int i = tid + u*256;
        int r = i / 20, c = i % 20;
        hA[u] = A[(size_t)(m0 + r)*K + c];
        int nn = n0 + r; if (nn >= N) nn = N - 1;
        hB[u] = Bw[(size_t)nn*K + c];
    }
    for (int kt = 0; kt < nkt; kt++) {
        #pragma unroll
        for (int u = 0; u < 5; u++) {
            int i = tid + u*256;
            int r = i / 20, c = i % 20;
            sA[c][r] = hA[u];
            sB[c][r] = hB[u];
        }
        __syncthreads();
        if (kt + 1 < nkt) {
            int k0 = (kt + 1) * 20;
            #pragma unroll
            for (int u = 0; u < 5; u++) {
                int i = tid + u*256;
                int r = i / 20, c = i % 20;
                hA[u] = A[(size_t)(m0 + r)*K + k0 + c];
                int nn = n0 + r; if (nn >= N) nn = N - 1;
                hB[u] = Bw[(size_t)nn*K + k0 + c];
            }
        }
        #pragma unroll
        for (int k = 0; k < 20; k++) {
            float4 a = *(const float4*)&sA[k][4*ty];
            float4 b = *(const float4*)&sB[k][4*tx];
            acc[0][0] += a.x*b.x; acc[0][1] += a.x*b.y; acc[0][2] += a.x*b.z; acc[0][3] += a.x*b.w;
            acc[1][0] += a.y*b.x; acc[1][1] += a.y*b.y; acc[1][2] += a.y*b.z; acc[1][3] += a.y*b.w;
            acc[2][0] += a.z*b.x; acc[2][1] += a.z*b.y; acc[2][2] += a.z*b.z; acc[2][3] += a.z*b.w;
            acc[3][0] += a.w*b.x; acc[3][1] += a.w*b.y; acc[3][2] += a.w*b.z; acc[3][3] += a.w*b.w;
        }
        __syncthreads();
    }
    #pragma unroll
    for (int i = 0; i < 4; i++) {
        int mm = m0 + 4*ty + i;
        #pragma unroll
        for (int j = 0; j < 4; j++) {
            int nn = n0 + 4*tx + j;
            if (nn < N) C[(size_t)mm*N + nn] = acc[i][j] + bias[nn];
        }
    }
}

// Both agg input projections in one launch (blockIdx.z selects f/b).
__global__ void gemm_nt2_dual(const float* __restrict__ A,
                              const float* __restrict__ Wf_, const float* __restrict__ bf,
                              const float* __restrict__ Wb_, const float* __restrict__ bb_,
                              float* __restrict__ Cf, float* __restrict__ Cb,
                              int M, int N, int K)
{
    const float* Bw   = blockIdx.z ? Wb_ : Wf_;
    const float* bias = blockIdx.z ? bb_ : bf;
    float* C          = blockIdx.z ? Cb  : Cf;
    __shared__ __align__(16) float sA[20][68];
    __shared__ __align__(16) float sB[20][68];
    int n0 = blockIdx.x * 64, m0 = blockIdx.y * 64;
    int tid = threadIdx.x, tx = tid & 15, ty = tid >> 4;
    float acc[4][4] = {};
    float hA[5], hB[5];
    int nkt = K / 20;

    #pragma unroll
    for (int u = 0; u < 5; u++) {
        int i = tid + u*256;
        int r = i / 20, c = i % 20;
        hA[u] = A[(size_t)(m0 + r)*K + c];
        int nn = n0 + r; if (nn >= N) nn = N - 1;
        hB[u] = Bw[(size_t)nn*K + c];
    }
    for (int kt = 0; kt < nkt; kt++) {
        #pragma unroll
        for (int u = 0; u < 5; u++) {
            int i = tid + u*256;
            int r = i / 20, c = i % 20;
            sA[c][r] = hA[u];
            sB[c][r] = hB[u];
        }
        __syncthreads();
        if (kt + 1 < nkt) {
            int k0 = (kt + 1) * 20;
            #pragma unroll
            for (int u = 0; u < 5; u++) {
                int i = tid + u*256;
                int r = i / 20, c = i % 20;
                hA[u] = A[(size_t)(m0 + r)*K + k0 + c];
                int nn = n0 + r; if (nn >= N) nn = N - 1;
                hB[u] = Bw[(size_t)nn*K + k0 + c];
            }
        }
        #pragma unroll
        for (int k = 0; k < 20; k++) {
            float4 a = *(const float4*)&sA[k][4*ty];
            float4 b = *(const float4*)&sB[k][4*tx];
            acc[0][0] += a.x*b.x; acc[0][1] += a.x*b.y; acc[0][2] += a.x*b.z; acc[0][3] += a.x*b.w;
            acc[1][0] += a.y*b.x; acc[1][1] += a.y*b.y; acc[1][2] += a.y*b.z; acc[1][3] += a.y*b.w;
            acc[2][0] += a.z*b.x; acc[2][1] += a.z*b.y; acc[2][2] += a.z*b.z; acc[2][3] += a.z*b.w;
            acc[3][0] += a.w*b.x; acc[3][1] += a.w*b.y; acc[3][2] += a.w*b.z; acc[3][3] += a.w*b.w;
        }
        __syncthreads();
    }
    #pragma unroll
    for (int i = 0; i < 4; i++) {
        int mm = m0 + 4*ty + i;
        #pragma unroll
        for (int j = 0; j < 4; j++) {
            int nn = n0 + 4*tx + j;
            if (nn < N) C[(size_t)mm*N + nn] = acc[i][j] + bias[nn];
        }
    }
}

// Head FC as tiled GEMM with bn fused into the A-load and relu epilogue.
// Y[M=128, N=600] = relu( bn(x)[M,K=600] @ W[N,K]^T + bias ).
// x split: if xb != null, col k<300 from xa[m*300+k] else xb[m*300+k-300];
// otherwise xa[m*600+k].
__global__ void gemm_bn(const float* __restrict__ xa, const float* __restrict__ xb,
                        const float* __restrict__ W, const float* __restrict__ bias,
                        const float* __restrict__ gamma, const float* __restrict__ beta,
                        float inv, float* __restrict__ Y, int N)
{
    const int K = 600;
    __shared__ __align__(16) float sA[20][68];
    __shared__ __align__(16) float sB[20][68];
    int n0 = blockIdx.x * 64, m0 = blockIdx.y * 64;
    int tid = threadIdx.x, tx = tid & 15, ty = tid >> 4;
    float acc[4][4] = {};
    float hA[5], hB[5];

    auto loadA = [&](int r, int k) -> float {
        int m = m0 + r;
        float xv;
        if (xb) xv = (k < 300) ? xa[m*300 + k] : xb[m*300 + k - 300];
        else    xv = xa[m*600 + k];
        return gamma[k]*xv*inv + beta[k];
    };

    #pragma unroll
    for (int u = 0; u < 5; u++) {
        int i = tid + u*256;
        int r = i / 20, c = i % 20;
        hA[u] = loadA(r, c);
        int nn = n0 + r; if (nn >= N) nn = N - 1;
        hB[u] = W[(size_t)nn*K + c];
    }
    for (int kt = 0; kt < 30; kt++) {
        #pragma unroll
        for (int u = 0; u < 5; u++) {
            int i = tid + u*256;
            int r = i / 20, c = i % 20;
            sA[c][r] = hA[u];
            sB[c][r] = hB[u];
        }
        __syncthreads();
        if (kt < 29) {
            int k0 = (kt + 1) * 20;
            #pragma unroll
            for (int u = 0; u < 5; u++) {
                int i = tid + u*256;
                int r = i / 20, c = i % 20;
                hA[u] = loadA(r, k0 + c);
                int nn = n0 + r; if (nn >= N) nn = N - 1;
                hB[u] = W[(size_t)nn*K + k0 + c];
            }
        }
        #pragma unroll
        for (int k = 0; k < 20; k++) {
            float4 a = *(const float4*)&sA[k][4*ty];
            float4 b = *(const float4*)&sB[k][4*tx];
            acc[0][0] += a.x*b.x; acc[0][1] += a.x*b.y; acc[0][2] += a.x*b.z; acc[0][3] += a.x*b.w;
            acc[1][0] += a.y*b.x; acc[1][1] += a.y*b.y; acc[1][2] += a.y*b.z; acc[1][3] += a.y*b.w;
            acc[2][0] += a.z*b.x; acc[2][1] += a.z*b.y; acc[2][2] += a.z*b.z; acc[2][3] += a.z*b.w;
            acc[3][0] += a.w*b.x; acc[3][1] += a.w*b.y; acc[3][2] += a.w*b.z; acc[3][3] += a.w*b.w;
        }
        __syncthreads();
    }
    #pragma unroll
    for (int i = 0; i < 4; i++) {
        int mm = m0 + 4*ty + i;
        #pragma unroll
        for (int j = 0; j < 4; j++) {
            int nn = n0 + 4*tx + j;
            if (nn < N) {
                float v = acc[i][j] + bias[nn];
                Y[(size_t)mm*N + nn] = (v < 0.f) ? 0.f : v;
            }
        }
    }
}

// One LSTM timestep, both directions (blockIdx.z). (round-7/12 proven version)
template<int RT, int RPT>
__global__ void __launch_bounds__(256, 2) lstm_step4(
    const float* __restrict__ xg_f, const float* __restrict__ xg_b,
    const float* __restrict__ Whh_f, const float* __restrict__ Whh_b,
    const float* __restrict__ hp_f, const float* __restrict__ hp_b,
    float* __restrict__ ho_f, float* __restrict__ ho_b,
    float* __restrict__ c_f, float* __restrict__ c_b,
    int first)
{
    constexpr int NT = 256;
    constexpr int NH = (30*RT + NT - 1) / NT;
    constexpr int NW = (30*64 + NT - 1) / NT;

    int dir = blockIdx.z;
    const float* xg  = dir ? xg_b  : xg_f;
    const float* Whh = dir ? Whh_b : Whh_f;
    const float* hp  = dir ? hp_b  : hp_f;
    float* ho = dir ? ho_b : ho_f;
    float* cs = dir ? c_b  : c_f;

    int j0 = blockIdx.x * 16;
    int r0 = blockIdx.y * RT;
    int tx = threadIdx.x;
    int ty = threadIdx.y;
    int tid = ty * 16 + tx;

    __shared__ __align__(16) float sH[30][RT + 4];
    __shared__ __align__(16) float sW[30][68];
    float acc[4][RPT] = {};

    if (!first) {
        float hA[NH], hW[NW];
        #pragma unroll
        for (int u = 0; u < NH; u++) {
            int i = tid + u*NT;
            if (i < 30*RT) { int r = i/30, c = i%30; hA[u] = hp[(size_t)(r0 + r)*HD + c]; }
        }
        #pragma unroll
        for (int u = 0; u < NW; u++) {
            int i = tid + u*NT;
            if (i < 30*64) {
                int rr = i/30, c = i%30;
                int gg = rr & 3, jl = rr >> 2;
                int jj = j0 + jl; if (jj >= HD) jj = HD - 1;
                hW[u] = Whh[(size_t)(gg*HD + jj)*HD + c];
            }
        }
        for (int kt = 0; kt < 10; kt++) {
            #pragma unroll
            for (int u = 0; u < NH; u++) {
                int i = tid + u*NT;
                if (i < 30*RT) { int r = i/30, c = i%30; sH[c][r] = hA[u]; }
            }
            #pragma unroll
            for (int u = 0; u < NW; u++) {
                int i = tid + u*NT;
                if (i < 30*64) { int rr = i/30, c = i%30; sW[c][rr] = hW[u]; }
            }
            __syncthreads();
            if (kt < 9) {
                int k0 = (kt + 1) * 30;
                #pragma unroll
                for (int u = 0; u < NH; u++) {
                    int i = tid + u*NT;
                    if (i < 30*RT) { int r = i/30, c = i%30; hA[u] = hp[(size_t)(r0 + r)*HD + k0 + c]; }
                }
                #pragma unroll
                for (int u = 0; u < NW; u++) {
                    int i = tid + u*NT;
                    if (i < 30*64) {
                        int rr = i/30, c = i%30;
                        int gg = rr & 3, jl = rr >> 2;
                        int jj = j0 + jl; if (jj >= HD) jj = HD - 1;
                        hW[u] = Whh[(size_t)(gg*HD + jj)*HD + k0 + c];
                    }
                }
            }
            #pragma unroll
            for (int k = 0; k < 30; k++) {
                float4 b = *(const float4*)&sW[k][4*tx];
                if constexpr (RPT == 4) {
                    float4 a = *(const float4*)&sH[k][4*ty];
                    acc[0][0] += b.x*a.x; acc[0][1] += b.x*a.y; acc[0][2] += b.x*a.z; acc[0][3] += b.x*a.w;
                    acc[1][0] += b.y*a.x; acc[1][1] += b.y*a.y; acc[1][2] += b.y*a.z; acc[1][3] += b.y*a.w;
                    acc[2][0] += b.z*a.x; acc[2][1] += b.z*a.y; acc[2][2] += b.z*a.z; acc[2][3] += b.z*a.w;
                    acc[3][0] += b.w*a.x; acc[3][1] += b.w*a.y; acc[3][2] += b.w*a.z; acc[3][3] += b.w*a.w;
                } else {
                    float2 a = *(const float2*)&sH[k][2*ty];
                    acc[0][0] += b.x*a.x; acc[0][1] += b.x*a.y;
                    acc[1][0] += b.y*a.x; acc[1][1] += b.y*a.y;
                    acc[2][0] += b.z*a.x; acc[2][1] += b.z*a.y;
                    acc[3][0] += b.w*a.x; acc[3][1] += b.w*a.y;
                }
            }
            __syncthreads();
        }
    }
    int j = j0 + tx;
    if (j < HD) {
        #pragma unroll
        for (int r = 0; r < RPT; r++) {
            int row = r0 + RPT*ty + r;
            const float* xr = xg + (size_t)row*GG + j;
            float gi = acc[0][r] + xr[0];
            float gf = acc[1][r] + xr[300];
            float gg = acc[2][r] + xr[600];
            float go = acc[3][r] + xr[900];
            float cp = first ? 0.f : cs[row*HD + j];
            float cn = sigmf(gf)*cp + sigmf(gi)*tanh_fast(gg);
            cs[row*HD + j] = cn;
            ho[row*HD + j] = sigmf(go)*tanh_fast(cn);
        }
    }
}

// Fused L2 + perspective-weighted norms, both pairs: grid (TT*BB, 2), 128 threads.
__global__ void l2pn_kernel(const float* __restrict__ hsf, const float* __restrict__ hsb,
                            const float* __restrict__ mp_W,
                            float* __restrict__ pnm, float* __restrict__ hnm,
                            float* __restrict__ Pl2, float* __restrict__ Hl2)
{
    int pair = blockIdx.y;
    const float* base = pair ? hsb : hsf;
    const float* Wm = mp_W + (pair ? 30000 : 6000);
    float* po = pnm + (size_t)pair*TT*BB*LL;
    float* ho = hnm + (size_t)pair*TT*BB*LL;
    float* Po = Pl2 + pair*TT*BB;
    float* Ho = Hl2 + pair*TT*BB;

    int tb = blockIdx.x;
    int t = tb / BB, b = tb % BB;
    int warp = threadIdx.x >> 5, lane = threadIdx.x & 31;
    const float* prow = base + (size_t)t*NN*HD + b*HD;
    const float* hrow = prow + BB*HD;
    float p2[10], h2[10];
    #pragma unroll
    for (int u = 0; u < 10; u++) {
        int h = lane + 32*u;
        float pv = (h < HD) ? prow[h] : 0.f;
        float hv = (h < HD) ? hrow[h] : 0.f;
        p2[u] = pv*pv; h2[u] = hv*hv;
    }
    if (warp < 2) {
        float s = 0.f;
        #pragma unroll
        for (int u = 0; u < 10; u++) s += (warp ? h2[u] : p2[u]);
        for (int o = 16; o; o >>= 1) s += __shfl_down_sync(0xffffffffu, s, o);
        if (lane == 0) (warp ? Ho : Po)[t*BB + b] = sqrtf(s);
    }
    for (int l = warp; l < LL; l += 4) {
        float ap = 0.f, ah = 0.f;
        #pragma unroll
        for (int u = 0; u < 10; u++) {
            int h = lane + 32*u;
            float wv = (h < HD) ? Wm[l*HD + h] : 0.f;
            float w2 = wv*wv;
            ap += p2[u]*w2; ah += h2[u]*w2;
        }
        for (int o = 16; o; o >>= 1) {
            ap += __shfl_down_sync(0xffffffffu, ap, o);
            ah += __shfl_down_sync(0xffffffffu, ah, o);
        }
        if (lane == 0) { po[tb*LL + l] = sqrtf(ap); ho[tb*LL + l] = sqrtf(ah); }
    }
}

// Cosine attention for both pairs and both directions: grid (BB, 2).
__global__ void att2_kernel(const float* __restrict__ hsf, const float* __restrict__ hsb,
                            const float* __restrict__ Pl2, const float* __restrict__ Hl2,
                            float* __restrict__ w1out, int* __restrict__ idx1out,
                            float* __restrict__ w3out, int* __restrict__ idx3out)
{
    int pair = blockIdx.y;
    const float* A = (pair ? hsb : hsf);
    const float* B = A + BB*HD;
    const float* Al2 = Pl2 + pair*TT*BB;
    const float* Bl2 = Hl2 + pair*TT*BB;
    float* w1o = w1out + (size_t)pair*BB*TT*TT;
    float* w3o = w3out + (size_t)pair*BB*TT*TT;
    int* i1o = idx1out + pair*BB*TT;
    int* i3o = idx3out + pair*BB*TT;

    int b = blockIdx.x;
    __shared__ __align__(16) float sP[20][68], sH[20][68];
    __shared__ float sAtt[64][65];
    __shared__ float sSumR[64];
    __shared__ float sSumC[64];
    int tid = threadIdx.x, tx = tid & 15, ty = tid >> 4;
    float acc[4][4] = {};
    const int TS = NN*HD;
    for (int kt = 0; kt < 15; kt++) {
        int k0 = kt*20;
        #pragma unroll
        for (int u = 0; u < 5; u++) {
            int i = tid + u*256;
            int r = i / 20, c = i % 20;
            sP[c][r] = A[(size_t)r*TS + b*HD + k0 + c];
            sH[c][r] = B[(size_t)r*TS + b*HD + k0 + c];
        }
        __syncthreads();
        #pragma unroll
        for (int k = 0; k < 20; k++) {
            float4 a = *(const float4*)&sP[k][4*ty];
            float4 bb = *(const float4*)&sH[k][4*tx];
            acc[0][0] += a.x*bb.x; acc[0][1] += a.x*bb.y; acc[0][2] += a.x*bb.z; acc[0][3] += a.x*bb.w;
            acc[1][0] += a.y*bb.x; acc[1][1] += a.y*bb.y; acc[1][2] += a.y*bb.z; acc[1][3] += a.y*bb.w;
            acc[2][0] += a.z*bb.x; acc[2][1] += a.z*bb.y; acc[2][2] += a.z*bb.z; acc[2][3] += a.z*bb.w;
            acc[3][0] += a.w*bb.x; acc[3][1] += a.w*bb.y; acc[3][2] += a.w*bb.z; acc[3][3] += a.w*bb.w;
        }
        __syncthreads();
    }
    #pragma unroll
    for (int i = 0; i < 4; i++) {
        int t = 4*ty + i;
        float pn = Al2[t*BB + b] + EPSF;
        #pragma unroll
        for (int j = 0; j < 4; j++) {
            int s = 4*tx + j;
            sAtt[t][s] = acc[i][j] / (pn * (Bl2[s*BB + b] + EPSF));
        }
    }
    __syncthreads();
    if (tid < 64) {
        float sum = 0.f, best = -1e30f; int bi = 0;
        for (int s = 0; s < 64; s++) {
            float v = sAtt[tid][s];
            sum += v;
            if (v > best) { best = v; bi = s; }
        }
        sSumR[tid] = sum + EPSF;
        i1o[b*64 + tid] = bi;
    } else if (tid < 128) {
        int t = tid - 64;
        float sum = 0.f, best = -1e30f; int bi = 0;
        for (int s = 0; s < 64; s++) {
            float v = sAtt[s][t];
            sum += v;
            if (v > best) { best = v; bi = s; }
        }
        sSumC[t] = sum + EPSF;
        i3o[b*64 + t] = bi;
    }
    __syncthreads();
    for (int i = tid; i < 4096; i += 256) {
        int t = i >> 6, s = i & 63;
        w1o[b*4096 + i] = sAtt[t][s] / sSumR[t];
        w3o[b*4096 + i] = sAtt[s][t] / sSumC[t];
    }
}

// hmean for all 4 (pair, dir) variants: grid (BB, 2, 2). y=dir, z=pair.
__global__ void hmean_kernel(const float* __restrict__ hsf, const float* __restrict__ hsb,
                             const float* __restrict__ w1, const float* __restrict__ w3,
                             float* __restrict__ hmean1, float* __restrict__ hmean3)
{
    int pair = blockIdx.z, dir = blockIdx.y;
    const float* base = pair ? hsb : hsf;
    const float* Hm = dir ? base : base + BB*HD;
    const float* w  = (dir ? w3 : w1) + (size_t)pair*BB*TT*TT;
    float* hout = (dir ? hmean3 : hmean1) + (size_t)pair*TT*BB*HD;

    int b = blockIdx.x;
    __shared__ float sW[64][65];
    int tid = threadIdx.x;
    for (int i = tid; i < 4096; i += 256) sW[i >> 6][i & 63] = w[b*4096 + i];
    __syncthreads();
    int tx = tid & 31, ty = tid >> 5;
    const int TS = NN*HD;
    for (int hc = 0; hc < 10; hc++) {
        int h = hc*32 + tx;
        bool valid = h < HD;
        float acc[8] = {};
        for (int s = 0; s < 64; s++) {
            float hv = valid ? Hm[(size_t)s*TS + b*HD + h] : 0.f;
            #pragma unroll
            for (int i = 0; i < 8; i++) acc[i] += sW[ty + 8*i][s] * hv;
        }
        if (valid) {
            #pragma unroll
            for (int i = 0; i < 8; i++) {
                int t = ty + 8*i;
                hout[((size_t)t*BB + b)*HD + h] = acc[i];
            }
        }
    }
}

// Shared-transpose maxp for both pairs: grid (BB, LL, 2).
__global__ void maxp3_kernel(const float* __restrict__ hsf, const float* __restrict__ hsb,
                             const float* __restrict__ mp_W,
                             const float* __restrict__ pnm, const float* __restrict__ hnm,
                             float* __restrict__ mout)
{
    int pair = blockIdx.z;
    const float* A = pair ? hsb : hsf;
    const float* B = A + BB*HD;
    const float* Wm = mp_W + (pair ? 30000 : 6000);
    const float* na = pnm + (size_t)pair*TT*BB*LL;
    const float* nb = hnm + (size_t)pair*TT*BB*LL;
    int moff1 = pair ? 80 : 0;
    int moff3 = pair ? 240 : 160;

    int b = blockIdx.x, l = blockIdx.y;
    __shared__ __align__(16) float sP[20][68], sH[20][68];
    __shared__ float sRedR[64][17];
    __shared__ float sRedC[64][17];
    int tid = threadIdx.x, tx = tid & 15, ty = tid >> 4;
    float acc[4][4] = {};
    const int TS = NN*HD;
    float hP[5], hHv[5];
    #pragma unroll
    for (int u = 0; u < 5; u++) {
        int i = tid + u*256;
        int r = i / 20, c = i % 20;
        float w = Wm[l*HD + c];
        hP[u]  = A[(size_t)r*TS + b*HD + c] * w * w;
        hHv[u] = B[(size_t)r*TS + b*HD + c];
    }
    for (int kt = 0; kt < 15; kt++) {
        #pragma unroll
        for (int u = 0; u < 5; u++) {
            int i = tid + u*256;
            int r = i / 20, c = i % 20;
            sP[c][r] = hP[u];
            sH[c][r] = hHv[u];
        }
        __syncthreads();
        if (kt < 14) {
            int k0 = (kt + 1)*20;
            #pragma unroll
            for (int u = 0; u < 5; u++) {
                int i = tid + u*256;
                int r = i / 20, c = i % 20;
                float w = Wm[l*HD + k0 + c];
                hP[u]  = A[(size_t)r*TS + b*HD + k0 + c] * w * w;
                hHv[u] = B[(size_t)r*TS + b*HD + k0 + c];
            }
        }
        #pragma unroll
        for (int k = 0; k < 20; k++) {
            float4 a = *(const float4*)&sP[k][4*ty];
            float4 bb = *(const float4*)&sH[k][4*tx];
            acc[0][0] += a.x*bb.x; acc[0][1] += a.x*bb.y; acc[0][2] += a.x*bb.z; acc[0][3] += a.x*bb.w;
            acc[1][0] += a.y*bb.x; acc[1][1] += a.y*bb.y; acc[1][2] += a.y*bb.z; acc[1][3] += a.y*bb.w;
            acc[2][0] += a.z*bb.x; acc[2][1] += a.z*bb.y; acc[2][2] += a.z*bb.z; acc[2][3] += a.z*bb.w;
            acc[3][0] += a.w*bb.x; acc[3][1] += a.w*bb.y; acc[3][2] += a.w*bb.z; acc[3][3] += a.w*bb.w;
        }
        __syncthreads();
    }
    float colmax[4] = {-1e30f, -1e30f, -1e30f, -1e30f};
    #pragma unroll
    for (int i = 0; i < 4; i++) {
        int t = 4*ty + i;
        float nat = na[(t*BB + b)*LL + l];
        float rmx = -1e30f;
        #pragma unroll
        for (int j = 0; j < 4; j++) {
            int s = 4*tx + j;
            float v = acc[i][j] / (nat * nb[(s*BB + b)*LL + l] + EPSF);
            rmx = fmaxf(rmx, v);
            colmax[j] = fmaxf(colmax[j], v);
        }
        sRedR[t][tx] = rmx;
    }
    #pragma unroll
    for (int j = 0; j < 4; j++) {
        int s = 4*tx + j;
        sRedC[s][ty] = colmax[j];
    }
    __syncthreads();
    if (tid < 64) {
        float mx = -1e30f;
        #pragma unroll
        for (int j = 0; j < 16; j++) mx = fmaxf(mx, sRedR[tid][j]);
        mout[((size_t)tid*BB + b)*ML + moff1 + 20 + l] = mx;
    } else if (tid < 128) {
        int s = tid - 64;
        float mx = -1e30f;
        #pragma unroll
        for (int j = 0; j < 16; j++) mx = fmaxf(mx, sRedC[s][j]);
        mout[((size_t)s*BB + b)*ML + moff3 + 20 + l] = mx;
    }
}

// full / attm / maxattm fused, all 4 (pair, dir) variants: grid (TT*BB, 2, 2).
__global__ void mpcomb_kernel(const float* __restrict__ hsf, const float* __restrict__ hsb,
                              const float* __restrict__ mp_W,
                              const float* __restrict__ hmean1, const float* __restrict__ hmean3,
                              const int* __restrict__ idx1, const int* __restrict__ idx3,
                              float* __restrict__ mout)
{
    int pair = blockIdx.z, dir = blockIdx.y;
    const float* base = pair ? hsb : hsf;
    const float* A = base;
    const float* Bm = base + BB*HD;
    const int TS = NN*HD;
    const float* Vb;
    if (pair == 0) Vb = dir ? (hsf + (size_t)63*TS) : (hsf + (size_t)63*TS + BB*HD);
    else           Vb = dir ? hsb : (hsb + BB*HD);
    const float* P  = dir ? Bm : A;
    const float* Hm = dir ? A  : Bm;
    const float* hmean = (dir ? hmean3 : hmean1) + (size_t)pair*TT*BB*HD;
    const int* idx = (dir ? idx3 : idx1) + pair*BB*TT;
    const float* Wf  = mp_W + (pair ? 24000 : 0);
    const float* Wa  = Wf + 12000;
    const float* Wma = Wf + 18000;
    int moff = pair ? (dir ? 240 : 80) : (dir ? 160 : 0);

    int tb = blockIdx.x;
    int t = tb / BB, b = tb % BB;
    int warp = threadIdx.x >> 5, lane = threadIdx.x & 31;
    int si = idx[b*64 + t];
    const float* prow = P  + (size_t)t*TS + b*HD;
    const float* vrow = Vb + (size_t)b*HD;
    const float* mrow = hmean + (size_t)tb*HD;
    const float* xrow = Hm + (size_t)si*TS + b*HD;
    float pv[10], p2[10], v2[10], phm[10], hm2[10], phx[10], hx2[10];
    #pragma unroll
    for (int u = 0; u < 10; u++) {
        int h = lane + 32*u;
        float p  = (h < HD) ? prow[h] : 0.f;
        float v  = (h < HD) ? vrow[h] : 0.f;
        float hm = (h < HD) ? mrow[h] : 0.f;
        float hx = (h < HD) ? xrow[h] : 0.f;
        pv[u] = p*v;  p2[u] = p*p;   v2[u] = v*v;
        phm[u] = p*hm; hm2[u] = hm*hm;
        phx[u] = p*hx; hx2[u] = hx*hx;
    }
    for (int l = warp; l < LL; l += 4) {
        float nf = 0, pf = 0, vf = 0, na = 0, pa = 0, qa = 0, nm = 0, pm = 0, qm = 0;
        #pragma unroll
        for (int u = 0; u < 10; u++) {
            int h = lane + 32*u;
            float wfv = (h < HD) ? Wf [l*HD + h] : 0.f; float wf2 = wfv*wfv;
            float wav = (h < HD) ? Wa [l*HD + h] : 0.f; float wa2 = wav*wav;
            float wmv = (h < HD) ? Wma[l*HD + h] : 0.f; float wm2 = wmv*wmv;
            nf += pv[u]*wf2;  pf += p2[u]*wf2;  vf += v2[u]*wf2;
            na += phm[u]*wa2; pa += p2[u]*wa2;  qa += hm2[u]*wa2;
            nm += phx[u]*wm2; pm += p2[u]*wm2;  qm += hx2[u]*wm2;
        }
        for (int o = 16; o; o >>= 1) {
            nf += __shfl_down_sync(0xffffffffu, nf, o);
            pf += __shfl_down_sync(0xffffffffu, pf, o);
            vf += __shfl_down_sync(0xffffffffu, vf, o);
            na += __shfl_down_sync(0xffffffffu, na, o);
            pa += __shfl_down_sync(0xffffffffu, pa, o);
            qa += __shfl_down_sync(0xffffffffu, qa, o);
            nm += __shfl_down_sync(0xffffffffu, nm, o);
            pm += __shfl_down_sync(0xffffffffu, pm, o);
            qm += __shfl_down_sync(0xffffffffu, qm, o);
        }
        if (lane == 0) {
            size_t basei = (size_t)tb*ML + moff;
            mout[basei + l]      = nf / (sqrtf(pf)*sqrtf(vf) + EPSF);
            mout[basei + 40 + l] = na / (sqrtf(pa)*sqrtf(qa) + EPSF);
            mout[basei + 60 + l] = nm / (sqrtf(pm)*sqrtf(qm) + EPSF);
        }
    }
}

// y = [relu]( bn(x) @ W^T + b ),  one row per block (tiny final layer only).
__global__ void fc_kernel(const float* __restrict__ xa, const float* __restrict__ xb,
                          int Kin,
                          const float* __restrict__ W, const float* __restrict__ bias,
                          const float* __restrict__ gamma, const float* __restrict__ beta,
                          float inv,
                          float* __restrict__ y, int Co, int relu)
{
    __shared__ float sx[600];
    int r = blockIdx.x;
    int half = Kin / 2;
    for (int k = threadIdx.x; k < Kin; k += blockDim.x) {
        float xv;
        if (xb) xv = (k < half) ? xa[r*half + k] : xb[r*half + k - half];
        else    xv = xa[r*Kin + k];
        sx[k] = gamma[k]*xv*inv + beta[k];
    }
    __syncthreads();
    for (int c = threadIdx.x; c < Co; c += blockDim.x) {
        float a = bias[c];
        for (int k = 0; k < Kin; k++) a += sx[k] * W[(size_t)c*Kin + k];
        y[r*Co + c] = (relu && a < 0.f) ? 0.f : a;
    }
}

// ---------------- host orchestration ----------------

extern "C" void kernel_launch(void* const* d_in, const int* in_sizes, int n_in,
                              void* d_out, int out_size)
{
    const int*   premise    = (const int*)d_in[0];
    const int*   hypothesis = (const int*)d_in[1];
    const float* embed_W    = (const float*)d_in[2];
    const float* cell_Wih   = (const float*)d_in[3];
    const float* cell_Whh   = (const float*)d_in[4];
    const float* cell_b     = (const float*)d_in[5];
    const float* mp_W       = (const float*)d_in[6];
    const float* agg_Wih_f  = (const float*)d_in[7];
    const float* agg_Whh_f  = (const float*)d_in[8];
    const float* agg_b_f    = (const float*)d_in[9];
    const float* agg_Wih_b  = (const float*)d_in[10];
    const float* agg_Whh_b  = (const float*)d_in[11];
    const float* agg_b_b    = (const float*)d_in[12];
    const float* bn_gamma   = (const float*)d_in[13];
    const float* bn_beta    = (const float*)d_in[14];
    const float* mlp_W1     = (const float*)d_in[15];
    const float* mlp_b1     = (const float*)d_in[16];
    const float* mlp_W2     = (const float*)d_in[17];
    const float* mlp_b2     = (const float*)d_in[18];
    const float* out_W      = (const float*)d_in[19];
    const float* out_b      = (const float*)d_in[20];
    float* outp = (float*)d_out;

    float *comb, *Xg, *hsf, *hsb, *cf, *cb, *mbuf, *aXf, *aXb;
    float *ahf, *ahb, *acf, *acb, *w1, *w3, *Pl2, *Hl2;
    float *hmean1, *hmean3, *pnm, *hnm, *y1, *y2;
    int *idx1, *idx3;
    cudaGetSymbolAddress((void**)&comb, g_comb);
    cudaGetSymbolAddress((void**)&Xg,   g_Xg);
    cudaGetSymbolAddress((void**)&hsf,  g_hsf);
    cudaGetSymbolAddress((void**)&hsb,  g_hsb);
    cudaGetSymbolAddress((void**)&cf,   g_cf);
    cudaGetSymbolAddress((void**)&cb,   g_cb);
    cudaGetSymbolAddress((void**)&mbuf, g_m);
    cudaGetSymbolAddress((void**)&aXf,  g_aXf);
    cudaGetSymbolAddress((void**)&aXb,  g_aXb);
    cudaGetSymbolAddress((void**)&ahf,  g_ahf);
    cudaGetSymbolAddress((void**)&ahb,  g_ahb);
    cudaGetSymbolAddress((void**)&acf,  g_acf);
    cudaGetSymbolAddress((void**)&acb,  g_acb);
    cudaGetSymbolAddress((void**)&w1,   g_w1);
    cudaGetSymbolAddress((void**)&w3,   g_w3);
    cudaGetSymbolAddress((void**)&idx1, g_idx1);
    cudaGetSymbolAddress((void**)&idx3, g_idx3);
    cudaGetSymbolAddress((void**)&Pl2,  g_Pl2);
    cudaGetSymbolAddress((void**)&Hl2,  g_Hl2);
    cudaGetSymbolAddress((void**)&hmean1, g_hmean1);
    cudaGetSymbolAddress((void**)&hmean3, g_hmean3);
    cudaGetSymbolAddress((void**)&pnm,  g_pnm);
    cudaGetSymbolAddress((void**)&hnm,  g_hnm);
    cudaGetSymbolAddress((void**)&y1,   g_y1);
    cudaGetSymbolAddress((void**)&y2,   g_y2);

    // 1. embedding gather -> comb (T,256,300)
    embed_kernel<<<(TT*NN*DD + 255)/256, 256>>>(premise, hypothesis, embed_W, comb);

    // 2. input projection for LSTM1, all timesteps at once
    gemm_nt2<<<dim3(19, 256), 256>>>(comb, cell_Wih, cell_b, Xg, TT*NN, GG, DD);

    // 3. BiLSTM1 recurrence (64 steps; both directions per launch)
    const int TS = NN*HD;
    for (int s = 0; s < 64; s++) {
        int first = (s == 0);
        const float* hpf = first ? nullptr : hsf + (size_t)(s - 1)*TS;
        const float* hpb = first ? nullptr : hsb + (size_t)(64 - s)*TS;
        lstm_step4<64, 4><<<dim3(19, 4, 2), dim3(16, 16)>>>(
            Xg + (size_t)s*NN*GG, Xg + (size_t)(63 - s)*NN*GG,
            cell_Whh, cell_Whh,
            hpf, hpb,
            hsf + (size_t)s*TS, hsb + (size_t)(63 - s)*TS,
            cf, cb, first);
    }

    // 4. multi-perspective matching — both transpose pairs per launch
    l2pn_kernel <<<dim3(TT*BB, 2), 128>>>(hsf, hsb, mp_W, pnm, hnm, Pl2, Hl2);
    att2_kernel <<<dim3(BB, 2), 256>>>(hsf, hsb, Pl2, Hl2, w1, idx1, w3, idx3);
    hmean_kernel<<<dim3(BB, 2, 2), 256>>>(hsf, hsb, w1, w3, hmean1, hmean3);
    maxp3_kernel<<<dim3(BB, LL, 2), 256>>>(hsf, hsb, mp_W, pnm, hnm, mbuf);
    mpcomb_kernel<<<dim3(TT*BB, 2, 2), 128>>>(hsf, hsb, mp_W, hmean1, hmean3,
                                              idx1, idx3, mbuf);

    // 5. aggregation input projections (both in one launch)
    gemm_nt2_dual<<<dim3(19, 128, 2), 256>>>(mbuf, agg_Wih_f, agg_b_f,
                                             agg_Wih_b, agg_b_b,
                                             aXf, aXb, TT*BB, GG, ML);

    // 6. aggregation BiLSTM (need only final hidden states; double-buffered h)
    for (int s = 0; s < 64; s++) {
        int first = (s == 0);
        int pi = s & 1, po = (s + 1) & 1;
        lstm_step4<32, 2><<<dim3(19, 4, 2), dim3(16, 16)>>>(
            aXf + (size_t)s*BB*GG, aXb + (size_t)(63 - s)*BB*GG,
            agg_Whh_f, agg_Whh_b,
            first ? nullptr : ahf + pi*BB*HD, first ? nullptr : ahb + pi*BB*HD,
            ahf + po*BB*HD, ahb + po*BB*HD,
            acf, acb, first);
    }
    const float* af = ahf;
    const float* ab = ahb;

    // 7. head: bn+fc+relu as tiled GEMM (fc1, fc2), tiny final layer on fc_kernel
    float inv = (float)(1.0 / sqrt(1.0 + 1e-5));
    gemm_bn<<<dim3(10, 2), 256>>>(af, ab, mlp_W1, mlp_b1,
                                  bn_gamma,       bn_beta,       inv, y1, 600);
    gemm_bn<<<dim3(10, 2), 256>>>(y1, nullptr, mlp_W2, mlp_b2,
                                  bn_gamma + 600, bn_beta + 600, inv, y2, 600);
    fc_kernel<<<BB, 256>>>(y2, nullptr, 600, out_W, out_b,
                           bn_gamma + 1200, bn_beta + 1200, inv, outp, 3, 0);
}